// round 10
// baseline (speedup 1.0000x reference)
#include <cuda_runtime.h>

#define B_ 64
#define N_ 1024
#define M_ 1024
#define Q_ 256          // float4 quads per row
#define QH 128          // quads per half-row (per warp of a pair)
#define EPSF 1e-4f
#define NT 128          // 4 warps = 2 pairs per block
#define RG 8            // rows per item
#define NG 128          // N_/RG
#define UH 4            // quads per lane per half
#define GMAX 32         // max blocks per batch group
#define PMAX 64         // max pairs per group (= 2*GMAX) = partial slots

__device__ float g_part[B_][PMAX][M_];   // 16 MB: per-pair column partials
__device__ float g_c[B_][M_];            // per-batch column factors
__device__ unsigned g_arr[B_];           // per-batch barrier arrive
__device__ volatile unsigned g_rel[B_];  // per-batch barrier release (monotone)

__device__ __forceinline__ void batch_sync(int b, int G) {
    __syncthreads();
    if (threadIdx.x == 0) {
        __threadfence();
        unsigned gen = g_rel[b];
        __threadfence();
        if (atomicAdd(&g_arr[b], 1u) == (unsigned)G - 1) {
            g_arr[b] = 0;
            __threadfence();
            g_rel[b] = gen + 1;
        } else {
            while (g_rel[b] == gen) __nanosleep(32);
        }
    }
    __syncthreads();
}

__device__ __forceinline__ float warp_sum(float v) {
#pragma unroll
    for (int o = 16; o; o >>= 1) v += __shfl_xor_sync(0xffffffffu, v, o);
    return v;
}
__device__ __forceinline__ void warp_sum2(float& a, float& b) {
#pragma unroll
    for (int o = 16; o; o >>= 1) {
        a += __shfl_xor_sync(0xffffffffu, a, o);
        b += __shfl_xor_sync(0xffffffffu, b, o);
    }
}

// pair barrier inside a block: pair 0 -> id 1 (threads 0-63), pair 1 -> id 2
#define BARP(p) asm volatile("bar.sync %0, 64;" :: "r"(1 + (p)) : "memory")

__device__ __forceinline__ unsigned long long wfun(int nr, int nc) {
    return 1024ULL * (unsigned)nc + 5ULL * (unsigned)nr * (unsigned)nc +
           (1ULL << 20);
}

struct Shm {
    int b, rank, G, nr, nc;
    float cs[4];                 // per-warp csum halves
    float xch[2][2][2][2];       // [pair][buf][half][rowInChunk]
};

// ---------------------------------------------------------------------------
__global__ void __launch_bounds__(NT, 5)
sinkhorn_kernel(const float* __restrict__ s, const int* __restrict__ nrows,
                const int* __restrict__ ncols, float* __restrict__ out) {
    __shared__ Shm sh;
    const int tid = threadIdx.x;
    const int lane = tid & 31;
    const int w = tid >> 5;          // warp in block 0..3
    const int pair = tid >> 6;       // 0..1
    const int half = (tid >> 5) & 1; // 0..1

    // ---- deterministic device-side group assignment ----
    if (tid == 0) {
        unsigned long long tot = 0;
        for (int k = 0; k < B_; k++)
            tot += wfun(__ldg(nrows + k), __ldg(ncols + k));
        int i = blockIdx.x;
        unsigned long long R = (unsigned long long)(gridDim.x - B_);
        int b, rank;
        if (i < B_) { b = i; rank = 0; }
        else {
            unsigned long long r = (unsigned long long)(i - B_);
            unsigned long long pref = 0;
            b = B_ - 1; rank = 0;
            for (int k = 0; k < B_; k++) {
                unsigned long long e0 = R * pref / tot;
                pref += wfun(__ldg(nrows + k), __ldg(ncols + k));
                unsigned long long e1 = R * pref / tot;
                if (r >= e0 && r < e1) { b = k; rank = 1 + (int)(r - e0); break; }
            }
        }
        unsigned long long pb = 0;
        int nr = 0, nc = 0;
        for (int k = 0; k < B_; k++) {
            int nrk = __ldg(nrows + k), nck = __ldg(ncols + k);
            if (k < b) pb += wfun(nrk, nck);
            if (k == b) { nr = nrk; nc = nck; }
        }
        unsigned long long e0 = R * pb / tot;
        unsigned long long e1 = R * (pb + wfun(nr, nc)) / tot;
        int G = 1 + (int)(e1 - e0);
        sh.b = b; sh.rank = rank; sh.G = (G > GMAX) ? GMAX : G;
        sh.nr = nr; sh.nc = nc;
    }
    __syncthreads();
    const int b = sh.b, rank = sh.rank, G = sh.G;
    const int nr = sh.nr, nc = sh.nc;
    if (rank >= G) return;           // capped-out block: idle

    const int P2 = 2 * G;                  // pairs in group = partial slots
    const int gp = rank * 2 + pair;        // my pair's global index / slot
    const int gtid = rank * NT + tid;
    const int gthreads = G * NT;
    const int nq = (nc + 3) >> 2;
    const int NVG = (nr + RG - 1) / RG;    // valid row-groups
    const int qoff = half * QH;

    const float4* sB = reinterpret_cast<const float4*>(s) + (size_t)b * N_ * Q_;
    float4* oB = reinterpret_cast<float4*>(out) + (size_t)b * N_ * Q_;
    float4* myp = reinterpret_cast<float4*>(&g_part[b][gp][0]) + qoff;
    const float4* cb = reinterpret_cast<const float4*>(&g_c[b][0]) + qoff;

    // ================= phase 0: iter-0 column partials (ALL rows) ==========
    {
        float4 acc[UH];
#pragma unroll
        for (int u = 0; u < UH; u++) acc[u] = make_float4(0.f, 0.f, 0.f, 0.f);
        for (int rg = gp; rg < NG; rg += P2) {
            const float4* sp = sB + (size_t)rg * RG * Q_ + qoff;
            for (int r = 0; r < RG; r += 2) {
#pragma unroll
                for (int u = 0; u < UH; u++) {
                    if (qoff + lane + 32 * u < nq) {
                        float4 v0 = __ldg(sp + r * Q_ + lane + 32 * u);
                        float4 v1 = __ldg(sp + (r + 1) * Q_ + lane + 32 * u);
                        acc[u].x += v0.x + v1.x; acc[u].y += v0.y + v1.y;
                        acc[u].z += v0.z + v1.z; acc[u].w += v0.w + v1.w;
                    }
                }
            }
        }
#pragma unroll
        for (int u = 0; u < UH; u++)
            if (qoff + lane + 32 * u < nq) __stcg(myp + lane + 32 * u, acc[u]);
    }
    batch_sync(b, G);

    // ================= finalize (FIRST) ====================================
    for (int j = gtid; j < M_; j += gthreads) {
        if (j >= nc) { __stcg(&g_c[b][j], 0.f); continue; }
        float a0 = 0.f, a1 = 0.f, a2 = 0.f, a3 = 0.f;
        int p = 0;
        for (; p + 4 <= P2; p += 4) {
            a0 += __ldcg(&g_part[b][p + 0][j]);
            a1 += __ldcg(&g_part[b][p + 1][j]);
            a2 += __ldcg(&g_part[b][p + 2][j]);
            a3 += __ldcg(&g_part[b][p + 3][j]);
        }
        for (; p < P2; p++) a0 += __ldcg(&g_part[b][p][j]);
        float sum = ((a0 + a1) + (a2 + a3)) + (float)N_ * EPSF;
        __stcg(&g_c[b][j], sum > 0.f ? __fdividef(1.f, sum) : 0.f);
    }
    batch_sync(b, G);

    // ================= iters 1..8: 4 fused row+col passes ==================
#pragma unroll 1
    for (int k = 0; k < 4; k++) {
        // stage c + csum once per pass
        float4 c[UH];
        float csl = 0.f;
#pragma unroll
        for (int u = 0; u < UH; u++) {
            c[u] = __ldcg(cb + lane + 32 * u);       // 0 beyond nc
            csl += (c[u].x + c[u].y) + (c[u].z + c[u].w);
        }
        csl = warp_sum(csl);
        if (lane == 0) sh.cs[w] = csl;
        __syncthreads();
        float ecs = EPSF * (sh.cs[pair * 2] + sh.cs[pair * 2 + 1]);

        float4 acc[UH];
#pragma unroll
        for (int u = 0; u < UH; u++) acc[u] = make_float4(0.f, 0.f, 0.f, 0.f);
        float rsum = 0.f;

        for (int rg = gp; rg < NVG; rg += P2) {
            int i0 = rg * RG;
            int rows = min(RG, nr - i0);
            const float4* sp = sB + (size_t)i0 * Q_ + qoff;
            int r = 0;
            for (; r + 2 <= rows; r += 2) {
                int buf = (r >> 1) & 1;
                float4 v0[UH], v1[UH];
                float rs0 = 0.f, rs1 = 0.f;
#pragma unroll
                for (int u = 0; u < UH; u++) {
                    v0[u] = make_float4(0.f, 0.f, 0.f, 0.f);
                    v1[u] = v0[u];
                    if (qoff + lane + 32 * u < nq) {
                        v0[u] = __ldg(sp + r * Q_ + lane + 32 * u);
                        v1[u] = __ldg(sp + (r + 1) * Q_ + lane + 32 * u);
                    }
                    rs0 += (v0[u].x * c[u].x + v0[u].y * c[u].y) +
                           (v0[u].z * c[u].z + v0[u].w * c[u].w);
                    rs1 += (v1[u].x * c[u].x + v1[u].y * c[u].y) +
                           (v1[u].z * c[u].z + v1[u].w * c[u].w);
                }
                warp_sum2(rs0, rs1);
                if (lane == 0) {
                    sh.xch[pair][buf][half][0] = rs0;
                    sh.xch[pair][buf][half][1] = rs1;
                }
                BARP(pair);
                float t0 = sh.xch[pair][buf][0][0] + sh.xch[pair][buf][1][0] + ecs;
                float t1 = sh.xch[pair][buf][0][1] + sh.xch[pair][buf][1][1] + ecs;
                float ri0 = t0 > 0.f ? __fdividef(1.f, t0) : 0.f;
                float ri1 = t1 > 0.f ? __fdividef(1.f, t1) : 0.f;
                rsum += ri0 + ri1;
#pragma unroll
                for (int u = 0; u < UH; u++) {
                    acc[u].x += v0[u].x * ri0 + v1[u].x * ri1;
                    acc[u].y += v0[u].y * ri0 + v1[u].y * ri1;
                    acc[u].z += v0[u].z * ri0 + v1[u].z * ri1;
                    acc[u].w += v0[u].w * ri0 + v1[u].w * ri1;
                }
            }
            if (r < rows) {
                int buf = (r >> 1) & 1;
                float4 v0[UH];
                float rs0 = 0.f;
#pragma unroll
                for (int u = 0; u < UH; u++) {
                    v0[u] = make_float4(0.f, 0.f, 0.f, 0.f);
                    if (qoff + lane + 32 * u < nq)
                        v0[u] = __ldg(sp + r * Q_ + lane + 32 * u);
                    rs0 += (v0[u].x * c[u].x + v0[u].y * c[u].y) +
                           (v0[u].z * c[u].z + v0[u].w * c[u].w);
                }
                rs0 = warp_sum(rs0);
                if (lane == 0) sh.xch[pair][buf][half][0] = rs0;
                BARP(pair);
                float t0 = sh.xch[pair][buf][0][0] + sh.xch[pair][buf][1][0] + ecs;
                float ri0 = t0 > 0.f ? __fdividef(1.f, t0) : 0.f;
                rsum += ri0;
#pragma unroll
                for (int u = 0; u < UH; u++) {
                    acc[u].x += v0[u].x * ri0; acc[u].y += v0[u].y * ri0;
                    acc[u].z += v0[u].z * ri0; acc[u].w += v0[u].w * ri0;
                }
            }
        }
        float er = EPSF * rsum;
#pragma unroll
        for (int u = 0; u < UH; u++) {
            if (qoff + lane + 32 * u < nq) {
                float4 o;
                o.x = acc[u].x + er; o.y = acc[u].y + er;
                o.z = acc[u].z + er; o.w = acc[u].w + er;
                __stcg(myp + lane + 32 * u, o);
            }
        }
        batch_sync(b, G);

        // ---- finalize (not first) ----
        for (int j = gtid; j < M_; j += gthreads) {
            if (j >= nc) { __stcg(&g_c[b][j], 0.f); continue; }
            float a0 = 0.f, a1 = 0.f, a2 = 0.f, a3 = 0.f;
            int p = 0;
            for (; p + 4 <= P2; p += 4) {
                a0 += __ldcg(&g_part[b][p + 0][j]);
                a1 += __ldcg(&g_part[b][p + 1][j]);
                a2 += __ldcg(&g_part[b][p + 2][j]);
                a3 += __ldcg(&g_part[b][p + 3][j]);
            }
            for (; p < P2; p++) a0 += __ldcg(&g_part[b][p][j]);
            float sum = ((a0 + a1) + (a2 + a3));
            __stcg(&g_c[b][j], sum > 0.f ? __fdividef(1.f, sum) : 0.f);
        }
        batch_sync(b, G);
    }

    // ================= final: iter-9 row norm + masked output ==============
    {
        const float4 z = make_float4(0.f, 0.f, 0.f, 0.f);
        float4 c[UH];
        float csl = 0.f;
#pragma unroll
        for (int u = 0; u < UH; u++) {
            c[u] = __ldcg(cb + lane + 32 * u);
            csl += (c[u].x + c[u].y) + (c[u].z + c[u].w);
        }
        csl = warp_sum(csl);
        if (lane == 0) sh.cs[w] = csl;
        __syncthreads();
        float ecs = EPSF * (sh.cs[pair * 2] + sh.cs[pair * 2 + 1]);

        for (int rg = gp; rg < NG; rg += P2) {
            int i0 = rg * RG;
            float4* op = oB + (size_t)i0 * Q_ + qoff;
            if (i0 >= nr) {
                for (int r = 0; r < RG; r++)
#pragma unroll
                    for (int u = 0; u < UH; u++)
                        __stcs(op + r * Q_ + lane + 32 * u, z);
                continue;
            }
            int rows = min(RG, nr - i0);
            const float4* sp = sB + (size_t)i0 * Q_ + qoff;
            int r = 0;
            for (; r + 2 <= rows; r += 2) {
                int buf = (r >> 1) & 1;
                float4 v0[UH], v1[UH];
                float rs0 = 0.f, rs1 = 0.f;
#pragma unroll
                for (int u = 0; u < UH; u++) {
                    v0[u] = z; v1[u] = z;
                    if (qoff + lane + 32 * u < nq) {
                        v0[u] = __ldg(sp + r * Q_ + lane + 32 * u);
                        v1[u] = __ldg(sp + (r + 1) * Q_ + lane + 32 * u);
                    }
                    rs0 += (v0[u].x * c[u].x + v0[u].y * c[u].y) +
                           (v0[u].z * c[u].z + v0[u].w * c[u].w);
                    rs1 += (v1[u].x * c[u].x + v1[u].y * c[u].y) +
                           (v1[u].z * c[u].z + v1[u].w * c[u].w);
                }
                warp_sum2(rs0, rs1);
                if (lane == 0) {
                    sh.xch[pair][buf][half][0] = rs0;
                    sh.xch[pair][buf][half][1] = rs1;
                }
                BARP(pair);
                float t0 = sh.xch[pair][buf][0][0] + sh.xch[pair][buf][1][0] + ecs;
                float t1 = sh.xch[pair][buf][0][1] + sh.xch[pair][buf][1][1] + ecs;
                float ri0 = t0 > 0.f ? __fdividef(1.f, t0) : 0.f;
                float ri1 = t1 > 0.f ? __fdividef(1.f, t1) : 0.f;
#pragma unroll
                for (int u = 0; u < UH; u++) {
                    float4 o0, o1;
                    o0.x = (v0[u].x + EPSF) * ri0 * c[u].x;   // c==0 past nc
                    o0.y = (v0[u].y + EPSF) * ri0 * c[u].y;
                    o0.z = (v0[u].z + EPSF) * ri0 * c[u].z;
                    o0.w = (v0[u].w + EPSF) * ri0 * c[u].w;
                    o1.x = (v1[u].x + EPSF) * ri1 * c[u].x;
                    o1.y = (v1[u].y + EPSF) * ri1 * c[u].y;
                    o1.z = (v1[u].z + EPSF) * ri1 * c[u].z;
                    o1.w = (v1[u].w + EPSF) * ri1 * c[u].w;
                    __stcs(op + r * Q_ + lane + 32 * u, o0);
                    __stcs(op + (r + 1) * Q_ + lane + 32 * u, o1);
                }
            }
            if (r < rows) {
                int buf = (r >> 1) & 1;
                float4 v0[UH];
                float rs0 = 0.f;
#pragma unroll
                for (int u = 0; u < UH; u++) {
                    v0[u] = z;
                    if (qoff + lane + 32 * u < nq)
                        v0[u] = __ldg(sp + r * Q_ + lane + 32 * u);
                    rs0 += (v0[u].x * c[u].x + v0[u].y * c[u].y) +
                           (v0[u].z * c[u].z + v0[u].w * c[u].w);
                }
                rs0 = warp_sum(rs0);
                if (lane == 0) sh.xch[pair][buf][half][0] = rs0;
                BARP(pair);
                float t0 = sh.xch[pair][buf][0][0] + sh.xch[pair][buf][1][0] + ecs;
                float ri0 = t0 > 0.f ? __fdividef(1.f, t0) : 0.f;
#pragma unroll
                for (int u = 0; u < UH; u++) {
                    float4 o0;
                    o0.x = (v0[u].x + EPSF) * ri0 * c[u].x;
                    o0.y = (v0[u].y + EPSF) * ri0 * c[u].y;
                    o0.z = (v0[u].z + EPSF) * ri0 * c[u].z;
                    o0.w = (v0[u].w + EPSF) * ri0 * c[u].w;
                    __stcs(op + r * Q_ + lane + 32 * u, o0);
                }
                r++;
            }
            for (; r < RG; r++)
#pragma unroll
                for (int u = 0; u < UH; u++)
                    __stcs(op + r * Q_ + lane + 32 * u, z);
        }
    }
}

extern "C" void kernel_launch(void* const* d_in, const int* in_sizes, int n_in,
                              void* d_out, int out_size) {
    const float* s   = (const float*)d_in[0];
    const int* nrows = (const int*)d_in[1];
    const int* ncols = (const int*)d_in[2];
    float* out       = (float*)d_out;

    int dev = 0;
    cudaGetDevice(&dev);
    int sms = 0;
    cudaDeviceGetAttribute(&sms, cudaDevAttrMultiProcessorCount, dev);
    int bpm = 0;
    cudaOccupancyMaxActiveBlocksPerMultiprocessor(&bpm, sinkhorn_kernel, NT, 0);
    int grid = sms * bpm;
    if (grid < B_ + 1) grid = B_ + 1;   // safety: ≥1 block per batch

    sinkhorn_kernel<<<grid, NT>>>(s, nrows, ncols, out);
}

// round 11
// speedup vs baseline: 1.1620x; 1.1620x over previous
#include <cuda_runtime.h>

#define B_ 64
#define N_ 1024
#define M_ 1024
#define Q_ 256          // float4 quads per row
#define QQ 64           // quads per quarter (per warp)
#define EPSF 1e-4f
#define NT 128          // 4 warps
#define RGF 16          // rows per fused/final item
#define NGF 64          // N_/RGF
#define U8 8            // quads per lane, full row

__device__ float g_part[B_][NGF][M_];    // 16 MB column partials
__device__ float g_c[B_][M_];            // column factors
__device__ unsigned g_ctr[8];
__device__ unsigned g_arrive;
__device__ volatile unsigned g_release;

__device__ __forceinline__ void grid_sync(unsigned nb) {
    __syncthreads();
    if (threadIdx.x == 0) {
        __threadfence();
        unsigned gen = g_release;
        __threadfence();
        if (atomicAdd(&g_arrive, 1) == nb - 1) {
            g_arrive = 0;
            __threadfence();
            g_release = gen + 1;
        } else {
            while (g_release == gen) __nanosleep(64);
        }
    }
    __syncthreads();
}

__device__ __forceinline__ float warp_sum(float v) {
#pragma unroll
    for (int o = 16; o; o >>= 1) v += __shfl_xor_sync(0xffffffffu, v, o);
    return v;
}
__device__ __forceinline__ void warp_sum2(float& a, float& b) {
#pragma unroll
    for (int o = 16; o; o >>= 1) {
        a += __shfl_xor_sync(0xffffffffu, a, o);
        b += __shfl_xor_sync(0xffffffffu, b, o);
    }
}

struct Shm {
    int sb[B_];          // batches sorted by nc desc (LPT)
    int vpre[B_ + 1];    // prefix of valid 16-row groups (sorted order)
    int snr[B_], snc[B_];
    int idx;             // block's stolen item
    float ri[RGF];       // per-row inverse sums
};

// ---------------------------------------------------------------------------
// phase0: iter-0 column partials over ALL rows. Warp items (b, rg16, quarter).
// ---------------------------------------------------------------------------
__device__ void phase0(const float4* __restrict__ s4, Shm* sh, int lane) {
    for (;;) {
        unsigned sv = 0;
        if (lane == 0) sv = atomicAdd(&g_ctr[0], 1u);
        int item = (int)__shfl_sync(0xffffffffu, sv, 0);
        if (item >= B_ * NGF * 4) break;
        int b = sh->sb[item >> 8];
        int rem = item & 255;
        int rg = rem >> 2, qi = rem & 3;
        int nq = (sh->snc[b] + 3) >> 2;
        int qoff = qi * QQ;
        if (qoff >= nq) continue;
        const float4* sp = s4 + (size_t)(b * N_ + rg * RGF) * Q_ + qoff;
        int q0 = qoff + lane, q1 = qoff + lane + 32;
        bool g0 = q0 < nq, g1 = q1 < nq;
        float4 a0 = make_float4(0.f, 0.f, 0.f, 0.f), a1 = a0;
        for (int r = 0; r < RGF; r += 2) {
            if (g0) {
                float4 v0 = __ldg(sp + r * Q_ + lane);
                float4 v1 = __ldg(sp + (r + 1) * Q_ + lane);
                a0.x += v0.x + v1.x; a0.y += v0.y + v1.y;
                a0.z += v0.z + v1.z; a0.w += v0.w + v1.w;
            }
            if (g1) {
                float4 v0 = __ldg(sp + r * Q_ + lane + 32);
                float4 v1 = __ldg(sp + (r + 1) * Q_ + lane + 32);
                a1.x += v0.x + v1.x; a1.y += v0.y + v1.y;
                a1.z += v0.z + v1.z; a1.w += v0.w + v1.w;
            }
        }
        float4* pp = reinterpret_cast<float4*>(&g_part[b][rg][0]) + qoff;
        if (g0) __stcg(pp + lane, a0);
        if (g1) __stcg(pp + lane + 32, a1);
    }
}

// ---------------------------------------------------------------------------
// finalize: c_j = 1/sum(group partials), masked. Fixed order, 8-way MLP.
// ---------------------------------------------------------------------------
template <int FIRST>
__device__ void finalize_phase(const Shm* sh, int gtid, int gthreads) {
    for (int t = gtid; t < B_ * M_; t += gthreads) {
        int b = t >> 10, j = t & (M_ - 1);
        if (j >= sh->snc[b]) { __stcg(&g_c[b][j], 0.f); continue; }
        int G = FIRST ? NGF : min(NGF, (sh->snr[b] + RGF - 1) / RGF);
        float a[8];
#pragma unroll
        for (int k = 0; k < 8; k++) a[k] = 0.f;
        int g = 0;
        for (; g + 8 <= G; g += 8) {
#pragma unroll
            for (int k = 0; k < 8; k++) a[k] += __ldcg(&g_part[b][g + k][j]);
        }
        for (; g < G; g++) a[0] += __ldcg(&g_part[b][g][j]);
        float sum = (((a[0] + a[1]) + (a[2] + a[3])) +
                     ((a[4] + a[5]) + (a[6] + a[7]))) +
                    (FIRST ? (float)N_ * EPSF : 0.f);
        __stcg(&g_c[b][j], sum > 0.f ? __fdividef(1.f, sum) : 0.f);
    }
}

// ---------------------------------------------------------------------------
// Phase A helper: warp w computes ri for its 4 rows of a 16-row item.
// Whole-row dots -> no inter-warp exchange. Writes sh->ri[r].
// ---------------------------------------------------------------------------
__device__ __forceinline__ void rowsums_A(const float4* __restrict__ sB,
                                          const float4* __restrict__ cb,
                                          Shm* sh, int i0, int rows,
                                          int nq, int lane, int w) {
    float4 c[U8];
    float cs = 0.f;
#pragma unroll
    for (int u = 0; u < U8; u++) {
        int q = lane + 32 * u;
        c[u] = make_float4(0.f, 0.f, 0.f, 0.f);
        if (q < nq) c[u] = __ldcg(cb + q);
        cs += (c[u].x + c[u].y) + (c[u].z + c[u].w);
    }
    cs = warp_sum(cs);
    float ecs = EPSF * cs;
    int rbase = 4 * w;
#pragma unroll
    for (int rr = 0; rr < 4; rr += 2) {
        int r0 = rbase + rr, r1 = r0 + 1;
        if (r0 >= rows) break;
        bool has1 = r1 < rows;
        const float4* sp0 = sB + (size_t)(i0 + r0) * Q_;
        const float4* sp1 = sB + (size_t)(i0 + r1) * Q_;
        float rs0 = 0.f, rs1 = 0.f;
#pragma unroll
        for (int u = 0; u < U8; u++) {
            int q = lane + 32 * u;
            if (q < nq) {
                float4 v0 = __ldg(sp0 + q);
                rs0 += (v0.x * c[u].x + v0.y * c[u].y) +
                       (v0.z * c[u].z + v0.w * c[u].w);
                if (has1) {
                    float4 v1 = __ldg(sp1 + q);
                    rs1 += (v1.x * c[u].x + v1.y * c[u].y) +
                           (v1.z * c[u].z + v1.w * c[u].w);
                }
            }
        }
        warp_sum2(rs0, rs1);
        if (lane == 0) {
            float t0 = rs0 + ecs;
            sh->ri[r0] = t0 > 0.f ? __fdividef(1.f, t0) : 0.f;
            if (has1) {
                float t1 = rs1 + ecs;
                sh->ri[r1] = t1 > 0.f ? __fdividef(1.f, t1) : 0.f;
            }
        }
    }
}

// ---------------------------------------------------------------------------
// Fused row+col pass: stolen 16-row items. A: warp-local row sums. Sync.
// B: warp-quarter column accumulate from L1-resident rows, write partial.
// ---------------------------------------------------------------------------
__device__ void fused_pass(const float4* __restrict__ s4, Shm* sh,
                           unsigned* ctr) {
    const int tid = threadIdx.x, lane = tid & 31, w = tid >> 5;
    const int count = sh->vpre[B_];
    for (;;) {
        __syncthreads();
        if (tid == 0) sh->idx = (int)atomicAdd(ctr, 1u);
        __syncthreads();
        int idx = sh->idx;
        if (idx >= count) break;
        int lo = 0, hi = B_;
        while (hi - lo > 1) {
            int mid = (lo + hi) >> 1;
            if (sh->vpre[mid] <= idx) lo = mid; else hi = mid;
        }
        int b = sh->sb[lo], rg = idx - sh->vpre[lo];
        int nr = sh->snr[b], nq = (sh->snc[b] + 3) >> 2;
        int i0 = rg * RGF, rows = min(RGF, nr - i0);
        const float4* sB = s4 + (size_t)b * N_ * Q_;
        const float4* cb = reinterpret_cast<const float4*>(&g_c[b][0]);

        rowsums_A(sB, cb, sh, i0, rows, nq, lane, w);
        __syncthreads();

        // Phase B: quarter accumulate
        float rsum = 0.f;
        for (int r = 0; r < rows; r++) rsum += sh->ri[r];
        int qb = w * QQ + lane;
        bool g0 = qb < nq, g1 = qb + 32 < nq;
        float4 a0 = make_float4(0.f, 0.f, 0.f, 0.f), a1 = a0;
        int r = 0;
        for (; r + 2 <= rows; r += 2) {
            float ri0 = sh->ri[r], ri1 = sh->ri[r + 1];
            const float4* sp0 = sB + (size_t)(i0 + r) * Q_;
            const float4* sp1 = sB + (size_t)(i0 + r + 1) * Q_;
            if (g0) {
                float4 v0 = __ldg(sp0 + qb), v1 = __ldg(sp1 + qb);
                a0.x += v0.x * ri0 + v1.x * ri1;
                a0.y += v0.y * ri0 + v1.y * ri1;
                a0.z += v0.z * ri0 + v1.z * ri1;
                a0.w += v0.w * ri0 + v1.w * ri1;
            }
            if (g1) {
                float4 v0 = __ldg(sp0 + qb + 32), v1 = __ldg(sp1 + qb + 32);
                a1.x += v0.x * ri0 + v1.x * ri1;
                a1.y += v0.y * ri0 + v1.y * ri1;
                a1.z += v0.z * ri0 + v1.z * ri1;
                a1.w += v0.w * ri0 + v1.w * ri1;
            }
        }
        if (r < rows) {
            float ri0 = sh->ri[r];
            const float4* sp0 = sB + (size_t)(i0 + r) * Q_;
            if (g0) {
                float4 v0 = __ldg(sp0 + qb);
                a0.x += v0.x * ri0; a0.y += v0.y * ri0;
                a0.z += v0.z * ri0; a0.w += v0.w * ri0;
            }
            if (g1) {
                float4 v0 = __ldg(sp0 + qb + 32);
                a1.x += v0.x * ri0; a1.y += v0.y * ri0;
                a1.z += v0.z * ri0; a1.w += v0.w * ri0;
            }
        }
        float er = EPSF * rsum;
        float4* pp = reinterpret_cast<float4*>(&g_part[b][rg][0]);
        if (g0) {
            float4 o; o.x = a0.x + er; o.y = a0.y + er;
            o.z = a0.z + er; o.w = a0.w + er;
            __stcg(pp + qb, o);
        }
        if (g1) {
            float4 o; o.x = a1.x + er; o.y = a1.y + er;
            o.z = a1.z + er; o.w = a1.w + er;
            __stcg(pp + qb + 32, o);
        }
    }
}

// ---------------------------------------------------------------------------
// Final: iter-9 row norm + masked output. Same A/B shape; B writes output.
// ---------------------------------------------------------------------------
__device__ void final_pass(const float4* __restrict__ s4,
                           float4* __restrict__ o4, Shm* sh) {
    const int tid = threadIdx.x, lane = tid & 31, w = tid >> 5;
    const float4 z = make_float4(0.f, 0.f, 0.f, 0.f);
    for (;;) {
        __syncthreads();
        if (tid == 0) sh->idx = (int)atomicAdd(&g_ctr[5], 1u);
        __syncthreads();
        int idx = sh->idx;
        if (idx >= B_ * NGF) break;
        int b = idx >> 6, rg = idx & (NGF - 1);
        int nr = sh->snr[b];
        int i0 = rg * RGF;
        int qb = w * QQ + lane;
        float4* op = o4 + (size_t)(b * N_ + i0) * Q_;
        if (i0 >= nr) {                    // whole group invalid: zero-fill
            for (int r = 0; r < RGF; r++) {
                __stcs(op + r * Q_ + qb, z);
                __stcs(op + r * Q_ + qb + 32, z);
            }
            continue;
        }
        int nq = (sh->snc[b] + 3) >> 2;
        int rows = min(RGF, nr - i0);
        const float4* sB = s4 + (size_t)b * N_ * Q_;
        const float4* cb = reinterpret_cast<const float4*>(&g_c[b][0]);

        rowsums_A(sB, cb, sh, i0, rows, nq, lane, w);
        __syncthreads();

        bool g0 = qb < nq, g1 = qb + 32 < nq;
        float4 c0 = g0 ? __ldcg(cb + qb) : z;
        float4 c1 = g1 ? __ldcg(cb + qb + 32) : z;
        for (int r = 0; r < RGF; r++) {
            float4 o0 = z, o1 = z;
            if (r < rows) {
                float ri = sh->ri[r];
                const float4* sp = sB + (size_t)(i0 + r) * Q_;
                if (g0) {
                    float4 v = __ldg(sp + qb);          // L1 hit
                    o0.x = (v.x + EPSF) * ri * c0.x;
                    o0.y = (v.y + EPSF) * ri * c0.y;
                    o0.z = (v.z + EPSF) * ri * c0.z;
                    o0.w = (v.w + EPSF) * ri * c0.w;
                }
                if (g1) {
                    float4 v = __ldg(sp + qb + 32);
                    o1.x = (v.x + EPSF) * ri * c1.x;
                    o1.y = (v.y + EPSF) * ri * c1.y;
                    o1.z = (v.z + EPSF) * ri * c1.z;
                    o1.w = (v.w + EPSF) * ri * c1.w;
                }
            }
            __stcs(op + r * Q_ + qb, o0);
            __stcs(op + r * Q_ + qb + 32, o1);
        }
    }
}

// ---------------------------------------------------------------------------
__global__ void __launch_bounds__(NT, 6)
sinkhorn_kernel(const float* __restrict__ s, const int* __restrict__ nrows,
                const int* __restrict__ ncols, float* __restrict__ out) {
    __shared__ Shm shm;
    const int tid = threadIdx.x;
    const int lane = tid & 31;
    const unsigned nb = gridDim.x;

    if (tid < B_) {
        shm.snr[tid] = __ldg(nrows + tid);
        shm.snc[tid] = __ldg(ncols + tid);
    }
    __syncthreads();
    if (tid < B_) {                     // rank sort by nc desc (LPT)
        int myc = shm.snc[tid];
        int rank = 0;
        for (int j = 0; j < B_; j++) {
            int cj = shm.snc[j];
            rank += (cj > myc) || (cj == myc && j < tid);
        }
        shm.sb[rank] = tid;
    }
    __syncthreads();
    if (tid <= B_) {                    // prefix of valid 16-row groups
        int a = 0;
        for (int k = 0; k < tid; k++)
            a += (shm.snr[shm.sb[k]] + RGF - 1) / RGF;
        shm.vpre[tid] = a;
    }
    __syncthreads();

    const float4* s4 = reinterpret_cast<const float4*>(s);
    float4* o4 = reinterpret_cast<float4*>(out);
    const int gtid = blockIdx.x * NT + tid;
    const int gthreads = nb * NT;

    phase0(s4, &shm, lane);             // iter 0 column partials
    grid_sync(nb);
    finalize_phase<1>(&shm, gtid, gthreads);
    // safe reset: ctr[0] done (sync above); ctr[1..5] not used until next sync
    if (blockIdx.x == 0 && tid < 8) g_ctr[tid] = 0;
    grid_sync(nb);

#pragma unroll 1
    for (int k = 0; k < 4; k++) {       // iters 1..8
        fused_pass(s4, &shm, &g_ctr[1 + k]);
        grid_sync(nb);
        finalize_phase<0>(&shm, gtid, gthreads);
        grid_sync(nb);
    }

    final_pass(s4, o4, &shm);           // iter 9 + masked output
}

extern "C" void kernel_launch(void* const* d_in, const int* in_sizes, int n_in,
                              void* d_out, int out_size) {
    const float* s   = (const float*)d_in[0];
    const int* nrows = (const int*)d_in[1];
    const int* ncols = (const int*)d_in[2];
    float* out       = (float*)d_out;

    int dev = 0;
    cudaGetDevice(&dev);
    int sms = 0;
    cudaDeviceGetAttribute(&sms, cudaDevAttrMultiProcessorCount, dev);
    int bpm = 0;
    cudaOccupancyMaxActiveBlocksPerMultiprocessor(&bpm, sinkhorn_kernel, NT, 0);
    int grid = sms * bpm;
    if (grid < 1) grid = 1;

    sinkhorn_kernel<<<grid, NT>>>(s, nrows, ncols, out);
}